// round 4
// baseline (speedup 1.0000x reference)
#include <cuda_runtime.h>
#include <cuda_fp16.h>
#include <cstdint>

#define BATCH 16
#define SEQ   256
#define DIM   512
#define G4    2048
#define LN_EPS 1e-5f

#define GROUPS 8                  // CTAs per batch = cluster size
#define NCTA  (BATCH*GROUPS)      // 128
#define TPB   512
#define ROWS_PER_CTA 256
#define ROWS_PER_WARP 16
#define NWARP 16

// SMEM-resident rows per warp: 7 (layer0) + 6 (layer1) = 13 rows
#define SR0 7
#define SR1 6
#define SMR (SR0+SR1)                          // 13
#define SM_ROWS (NWARP*SMR)                    // 208
#define SMEM_W_BYTES (SM_ROWS*DIM*2)           // 212992
#define OFF_GATES SMEM_W_BYTES                 // 2 layers * 2048 floats = 16384 B
#define OFF_H    (OFF_GATES + 2*G4*4)          // 2048 B
#define OFF_RED  (OFF_H + DIM*4)               // 128 B
#define OFF_STAT (OFF_RED + NWARP*8)           // 2 layers * 8 float2 = 128 B
#define OFF_C    (OFF_STAT + 2*GROUPS*8)       // 8 B
#define SMEM_TOTAL (OFF_C + 16)

// ---------------- static device scratch ----------------
__device__ __half  d_whh0h[(size_t)BATCH*G4*DIM];   // 32 MB fp16
__device__ __half  d_w1h  [(size_t)BATCH*G4*DIM];   // 32 MB fp16 (wih1+whh1)
__device__ float   d_pre0 [(size_t)BATCH*SEQ*G4];   // 32 MB: wih0@x + bih0 + bhh0
__device__ float   d_bias1[BATCH*G4];

// ---------------- small PTX helpers ----------------
__device__ __forceinline__ unsigned long long pk2f(float x, float y) {
    unsigned long long r; asm("mov.b64 %0,{%1,%2};" : "=l"(r) : "f"(x), "f"(y)); return r;
}
__device__ __forceinline__ float2 upk2f(unsigned long long v) {
    float2 f; asm("mov.b64 {%0,%1},%2;" : "=f"(f.x), "=f"(f.y) : "l"(v)); return f;
}
__device__ __forceinline__ unsigned long long pk2u(unsigned x, unsigned y) {
    unsigned long long r; asm("mov.b64 %0,{%1,%2};" : "=l"(r) : "r"(x), "r"(y)); return r;
}
__device__ __forceinline__ unsigned long long fma2(unsigned long long a,
                                                   unsigned long long b,
                                                   unsigned long long c) {
    unsigned long long d; asm("fma.rn.f32x2 %0,%1,%2,%3;" : "=l"(d) : "l"(a), "l"(b), "l"(c)); return d;
}
__device__ __forceinline__ unsigned smem_u32(const void* p) {
    unsigned a; asm("{ .reg .u64 t; cvta.to.shared.u64 t,%1; cvt.u32.u64 %0,t; }" : "=r"(a) : "l"(p)); return a;
}
__device__ __forceinline__ unsigned mapa_u32(unsigned a, unsigned rank) {
    unsigned r; asm("mapa.shared::cluster.u32 %0,%1,%2;" : "=r"(r) : "r"(a), "r"(rank)); return r;
}
__device__ __forceinline__ void stc_b64(unsigned a, unsigned long long v) {
    asm volatile("st.shared::cluster.b64 [%0],%1;" :: "r"(a), "l"(v) : "memory");
}
__device__ __forceinline__ unsigned cl_rank() {
    unsigned r; asm("mov.u32 %0, %%cluster_ctarank;" : "=r"(r)); return r;
}
__device__ __forceinline__ void cluster_sync_() {
    asm volatile("barrier.cluster.arrive.aligned;" ::: "memory");
    asm volatile("barrier.cluster.wait.aligned;" ::: "memory");
}

// ---------------- prep ----------------
__global__ void prep_kernel(const float* __restrict__ whh0,
                            const float* __restrict__ wih1,
                            const float* __restrict__ whh1,
                            const float* __restrict__ bih1,
                            const float* __restrict__ bhh1)
{
    size_t idx0 = blockIdx.x * blockDim.x + threadIdx.x;
    size_t stride = (size_t)gridDim.x * blockDim.x;
    const size_t NW4 = ((size_t)BATCH * G4 * DIM) / 4;
    const float4* w0v = (const float4*)whh0;
    const float4* u1v = (const float4*)wih1;
    const float4* v1v = (const float4*)whh1;
    uint2* o0 = (uint2*)d_whh0h;
    uint2* o1 = (uint2*)d_w1h;
    for (size_t i = idx0; i < NW4; i += stride) {
        float4 a = w0v[i];
        union { uint2 u; __half2 h[2]; } t0, t1;
        t0.h[0] = __floats2half2_rn(a.x, a.y);
        t0.h[1] = __floats2half2_rn(a.z, a.w);
        o0[i] = t0.u;
        float4 u = u1v[i], v = v1v[i];
        t1.h[0] = __floats2half2_rn(u.x + v.x, u.y + v.y);
        t1.h[1] = __floats2half2_rn(u.z + v.z, u.w + v.w);
        o1[i] = t1.u;
    }
    if (idx0 < BATCH * G4) d_bias1[idx0] = bih1[idx0] + bhh1[idx0];
}

// ---- SGEMM with packed f32x2 FMA ----
__global__ void __launch_bounds__(256) gemm_pre0(const float* __restrict__ x,
                                                 const float* __restrict__ wih0,
                                                 const float* __restrict__ bih0,
                                                 const float* __restrict__ bhh0)
{
    __shared__ float As[16][132];
    __shared__ float Bs[16][132];
    const int b  = blockIdx.y;
    const int mt = blockIdx.x & 15;
    const int nt = blockIdx.x >> 4;
    const float* A = wih0 + ((size_t)b * G4  + (size_t)mt * 128) * DIM;
    const float* B = x    + ((size_t)b * SEQ + (size_t)nt * 128) * DIM;
    const int tid = threadIdx.x;
    const int tr = tid & 15;
    const int tc = tid >> 4;

    unsigned long long acc2[8][4];
#pragma unroll
    for (int i = 0; i < 8; i++)
#pragma unroll
        for (int j = 0; j < 4; j++) acc2[i][j] = 0ull;

    for (int k0 = 0; k0 < DIM; k0 += 16) {
        __syncthreads();
#pragma unroll
        for (int p = 0; p < 2; p++) {
            int fid = tid + p * 256;
            int row = fid >> 2;
            int kq  = fid & 3;
            float4 va = *(const float4*)(A + (size_t)row * DIM + k0 + kq * 4);
            As[kq*4+0][row] = va.x; As[kq*4+1][row] = va.y;
            As[kq*4+2][row] = va.z; As[kq*4+3][row] = va.w;
            float4 vb = *(const float4*)(B + (size_t)row * DIM + k0 + kq * 4);
            Bs[kq*4+0][row] = vb.x; Bs[kq*4+1][row] = vb.y;
            Bs[kq*4+2][row] = vb.z; Bs[kq*4+3][row] = vb.w;
        }
        __syncthreads();
#pragma unroll
        for (int kk = 0; kk < 16; kk++) {
            float4 a0 = *(const float4*)&As[kk][tr*4];
            float4 a1 = *(const float4*)&As[kk][64 + tr*4];
            float4 b0 = *(const float4*)&Bs[kk][tc*4];
            float4 b1 = *(const float4*)&Bs[kk][64 + tc*4];
            float af[8] = {a0.x,a0.y,a0.z,a0.w,a1.x,a1.y,a1.z,a1.w};
            unsigned long long bp[4];
            bp[0] = pk2f(b0.x, b0.y); bp[1] = pk2f(b0.z, b0.w);
            bp[2] = pk2f(b1.x, b1.y); bp[3] = pk2f(b1.z, b1.w);
#pragma unroll
            for (int i = 0; i < 8; i++) {
                unsigned long long ap = pk2f(af[i], af[i]);
#pragma unroll
                for (int j = 0; j < 4; j++)
                    acc2[i][j] = fma2(ap, bp[j], acc2[i][j]);
            }
        }
    }

    float acc[8][8];
#pragma unroll
    for (int i = 0; i < 8; i++)
#pragma unroll
        for (int j = 0; j < 4; j++) {
            float2 f = upk2f(acc2[i][j]);
            acc[i][2*j] = f.x; acc[i][2*j+1] = f.y;
        }

    float biasv[8];
#pragma unroll
    for (int i = 0; i < 8; i++) {
        int j = mt * 128 + ((i < 4) ? (tr*4 + i) : (64 + tr*4 + (i - 4)));
        biasv[i] = bih0[b * G4 + j] + bhh0[b * G4 + j];
    }
#pragma unroll
    for (int jj = 0; jj < 8; jj++) {
        int t = nt * 128 + ((jj < 4) ? (tc*4 + jj) : (64 + tc*4 + (jj - 4)));
        float* dst = &d_pre0[((size_t)b * SEQ + t) * G4 + mt * 128];
        float4 v0, v1;
        v0.x = acc[0][jj] + biasv[0]; v0.y = acc[1][jj] + biasv[1];
        v0.z = acc[2][jj] + biasv[2]; v0.w = acc[3][jj] + biasv[3];
        v1.x = acc[4][jj] + biasv[4]; v1.y = acc[5][jj] + biasv[5];
        v1.z = acc[6][jj] + biasv[6]; v1.w = acc[7][jj] + biasv[7];
        *(float4*)(dst + tr * 4)      = v0;
        *(float4*)(dst + 64 + tr * 4) = v1;
    }
}

// ---------------- persistent LSTM kernel (clustered) ----------------
__device__ __forceinline__ float sigmoidf_(float x) {
    return __fdividef(1.f, 1.f + __expf(-x));
}

__device__ __forceinline__ float dot16(uint4 wa, uint4 wb, const float* hf) {
    float acc = 0.f;
    float2 f;
    f = __half22float2(*reinterpret_cast<__half2*>(&wa.x)); acc = fmaf(f.x, hf[0],  acc); acc = fmaf(f.y, hf[1],  acc);
    f = __half22float2(*reinterpret_cast<__half2*>(&wa.y)); acc = fmaf(f.x, hf[2],  acc); acc = fmaf(f.y, hf[3],  acc);
    f = __half22float2(*reinterpret_cast<__half2*>(&wa.z)); acc = fmaf(f.x, hf[4],  acc); acc = fmaf(f.y, hf[5],  acc);
    f = __half22float2(*reinterpret_cast<__half2*>(&wa.w)); acc = fmaf(f.x, hf[6],  acc); acc = fmaf(f.y, hf[7],  acc);
    f = __half22float2(*reinterpret_cast<__half2*>(&wb.x)); acc = fmaf(f.x, hf[8],  acc); acc = fmaf(f.y, hf[9],  acc);
    f = __half22float2(*reinterpret_cast<__half2*>(&wb.y)); acc = fmaf(f.x, hf[10], acc); acc = fmaf(f.y, hf[11], acc);
    f = __half22float2(*reinterpret_cast<__half2*>(&wb.z)); acc = fmaf(f.x, hf[12], acc); acc = fmaf(f.y, hf[13], acc);
    f = __half22float2(*reinterpret_cast<__half2*>(&wb.w)); acc = fmaf(f.x, hf[14], acc); acc = fmaf(f.y, hf[15], acc);
    return acc;
}

__global__ void __launch_bounds__(TPB, 1) __cluster_dims__(GROUPS, 1, 1)
lstm_kernel(const float* __restrict__ lnw, const float* __restrict__ lnb,
            float* __restrict__ out)
{
    extern __shared__ __align__(16) unsigned char smem_raw[];
    __half*  s_w     = (__half*)smem_raw;
    float*   s_gates = (float*)(smem_raw + OFF_GATES);   // [2][2048]
    float*   s_h     = (float*)(smem_raw + OFF_H);       // [512]
    float2*  s_red   = (float2*)(smem_raw + OFF_RED);    // [16]
    float2*  s_stat  = (float2*)(smem_raw + OFF_STAT);   // [2][8]
    float*   s_c     = (float*)(smem_raw + OFF_C);       // cm, cr

    const int b    = blockIdx.x >> 3;
    const unsigned rank = cl_rank();
    const int tid  = threadIdx.x;
    const int wid  = tid >> 5;
    const int lane = tid & 31;

    const __half* W0 = d_whh0h + (size_t)b * G4 * DIM;
    const __half* W1 = d_w1h   + (size_t)b * G4 * DIM;

    const int row0 = (int)rank * ROWS_PER_CTA + wid * ROWS_PER_WARP;  // global gate row base

    // DSMEM peer base addresses for gates / stats (linear offsets valid per-peer)
    const unsigned g_local_base = smem_u32(smem_raw) + OFF_GATES;
    const unsigned st_local_base = smem_u32(smem_raw) + OFF_STAT;

    // ---- fill SMEM weight cache: per warp, rows [0,7) of L0 and [0,6) of L1 ----
    {
        const int nU4 = SM_ROWS * (DIM / 8);   // 13312 uint4
        for (int i = tid; i < nU4; i += TPB) {
            int slot = i >> 6;
            int col  = i & 63;
            int w    = slot / SMR;
            int rem  = slot % SMR;
            int l    = (rem < SR0) ? 0 : 1;
            int r    = (rem < SR0) ? rem : (rem - SR0);
            const __half* W = (l == 0) ? W0 : W1;
            size_t grow = (size_t)((int)rank * ROWS_PER_CTA + w * ROWS_PER_WARP + r) * DIM;
            ((uint4*)s_w)[i] = ((const uint4*)(W + grow))[col];
        }
    }

    const float gw0 = __ldg(lnw + tid),       gb0 = __ldg(lnb + tid);
    const float gw1 = __ldg(lnw + DIM + tid), gb1 = __ldg(lnb + DIM + tid);

    float creg = 0.f;
    s_h[tid] = 0.f;
    __syncthreads();

    for (int t = 0; t < SEQ; t++) {
#pragma unroll
        for (int l = 0; l < 2; l++) {
            const __half* W   = (l == 0) ? W0 : W1;
            const float*  add = (l == 0) ? (d_pre0 + ((size_t)b * SEQ + t) * G4)
                                         : (d_bias1 + (size_t)b * G4);
            float* gl = s_gates + l * G4;
            const int SR    = (l == 0) ? SR0 : SR1;
            const int loff  = (l == 0) ? 0 : SR0;

            // ---- h into registers ----
            float hf[16];
            {
                const float4* hp = (const float4*)s_h;
                float4 v0 = hp[2*lane], v1 = hp[2*lane+1];
                float4 v2 = hp[64+2*lane], v3 = hp[64+2*lane+1];
                hf[0]=v0.x; hf[1]=v0.y; hf[2]=v0.z;  hf[3]=v0.w;
                hf[4]=v1.x; hf[5]=v1.y; hf[6]=v1.z;  hf[7]=v1.w;
                hf[8]=v2.x; hf[9]=v2.y; hf[10]=v2.z; hf[11]=v2.w;
                hf[12]=v3.x; hf[13]=v3.y; hf[14]=v3.z; hf[15]=v3.w;
            }
            float s1 = 0.f, s2 = 0.f;

            // ---- SMEM-resident rows ----
#pragma unroll
            for (int r = 0; r < ((l == 0) ? SR0 : SR1); r++) {
                const uint4* wp = (const uint4*)(s_w + (size_t)(wid * SMR + loff + r) * DIM);
                uint4 a0 = wp[lane];
                uint4 a1 = wp[32 + lane];
                float acc = dot16(a0, a1, hf);
#pragma unroll
                for (int o = 16; o > 0; o >>= 1)
                    acc += __shfl_down_sync(0xffffffffu, acc, o);
                if (lane == 0) {
                    float g = acc + __ldg(add + row0 + r);
                    gl[row0 + r] = g;
                    s1 += g; s2 = fmaf(g, g, s2);
                }
            }
            // ---- L2-streamed rows ----
            const uint4* wrow = (const uint4*)(W + (size_t)row0 * DIM);
#pragma unroll 3
            for (int r = SR; r < ROWS_PER_WARP; r++) {
                const uint4* wp = wrow + (size_t)r * 64;
                uint4 a0 = __ldcg(wp + lane);
                uint4 a1 = __ldcg(wp + 32 + lane);
                float acc = dot16(a0, a1, hf);
#pragma unroll
                for (int o = 16; o > 0; o >>= 1)
                    acc += __shfl_down_sync(0xffffffffu, acc, o);
                if (lane == 0) {
                    float g = acc + __ldg(add + row0 + r);
                    gl[row0 + r] = g;
                    s1 += g; s2 = fmaf(g, g, s2);
                }
            }
            if (lane == 0) s_red[wid] = make_float2(s1, s2);
            __syncthreads();

            // ---- DSMEM: broadcast my gate block (1 KB) to 7 peers + stats to all ----
            if (tid < 448) {
                int p   = tid >> 6;
                unsigned pr = p + (p >= (int)rank);
                int idx = tid & 63;
                unsigned off = (unsigned)((l * G4 + (int)rank * ROWS_PER_CTA) * 4 + idx * 16);
                uint4 v = *(const uint4*)(smem_raw + OFF_GATES + off);
                unsigned dst = mapa_u32(g_local_base + off, pr);
                stc_b64(dst,     pk2u(v.x, v.y));
                stc_b64(dst + 8, pk2u(v.z, v.w));
            }
            if (tid == 0) {
                float sa = 0.f, sb = 0.f;
#pragma unroll
                for (int i = 0; i < NWARP; i++) { sa += s_red[i].x; sb += s_red[i].y; }
                unsigned long long sv = pk2f(sa, sb);
                unsigned off = (unsigned)((l * GROUPS + (int)rank) * 8);
#pragma unroll
                for (unsigned p = 0; p < GROUPS; p++)
                    stc_b64(mapa_u32(st_local_base + off, p), sv);
            }
            cluster_sync_();

            // ---- pointwise (redundant per CTA; all operands local now) ----
            {
                const int d = tid;
                const float gw = (l == 0) ? gw0 : gw1;
                const float gb = (l == 0) ? gb0 : gb1;
                float m_[4], r_[4];
#pragma unroll
                for (int q = 0; q < 4; q++) {
                    float2 p0 = s_stat[l * GROUPS + 2*q];
                    float2 p1 = s_stat[l * GROUPS + 2*q + 1];
                    float s  = p0.x + p1.x;
                    float ss = p0.y + p1.y;
                    float m  = s * (1.f / 512.f);
                    float v  = fmaf(-m, m, ss * (1.f / 512.f));
                    m_[q] = m;
                    r_[q] = rsqrtf(v + LN_EPS);
                }
                float xi = gl[d];
                float xf = gl[512 + d];
                float xg = gl[1024 + d];
                float xo = gl[1536 + d];
                float iv = sigmoidf_(fmaf((xi - m_[0]) * r_[0], gw, gb));
                float fv = sigmoidf_(fmaf((xf - m_[1]) * r_[1], gw, gb));
                float gv = tanhf(    fmaf((xg - m_[2]) * r_[2], gw, gb));
                float ov = sigmoidf_(fmaf((xo - m_[3]) * r_[3], gw, gb));
                float cn = fmaf(fv, creg, iv * gv);
                creg = cn;

                float a = cn, c2 = cn * cn;
#pragma unroll
                for (int o = 16; o > 0; o >>= 1) {
                    a  += __shfl_down_sync(0xffffffffu, a, o);
                    c2 += __shfl_down_sync(0xffffffffu, c2, o);
                }
                if (lane == 0) s_red[wid] = make_float2(a, c2);
                __syncthreads();
                if (tid == 0) {
                    float sa = 0.f, sb = 0.f;
#pragma unroll
                    for (int i = 0; i < NWARP; i++) { sa += s_red[i].x; sb += s_red[i].y; }
                    float m = sa * (1.f / 512.f);
                    float v = fmaf(-m, m, sb * (1.f / 512.f));
                    s_c[0] = m;
                    s_c[1] = rsqrtf(v + LN_EPS);
                }
                __syncthreads();
                float hv = ov * tanhf(fmaf((cn - s_c[0]) * s_c[1], gw, gb));
                s_h[d] = hv;
                if (l == 1 && rank == 0)
                    out[((size_t)b * SEQ + t) * DIM + d] = hv;
                __syncthreads();
            }
        }
    }
}

extern "C" void kernel_launch(void* const* d_in, const int* in_sizes, int n_in,
                              void* d_out, int out_size) {
    const float* x    = (const float*)d_in[0];
    const float* wih0 = (const float*)d_in[1];
    const float* whh0 = (const float*)d_in[2];
    const float* bih0 = (const float*)d_in[3];
    const float* bhh0 = (const float*)d_in[4];
    const float* wih1 = (const float*)d_in[5];
    const float* whh1 = (const float*)d_in[6];
    const float* bih1 = (const float*)d_in[7];
    const float* bhh1 = (const float*)d_in[8];
    const float* ln_w = (const float*)d_in[9];
    const float* ln_b = (const float*)d_in[10];
    float* out = (float*)d_out;

    cudaFuncSetAttribute(lstm_kernel, cudaFuncAttributeMaxDynamicSharedMemorySize,
                         SMEM_TOTAL);

    prep_kernel<<<1024, 256>>>(whh0, wih1, whh1, bih1, bhh1);
    gemm_pre0<<<dim3(32, 16), 256>>>(x, wih0, bih0, bhh0);
    lstm_kernel<<<NCTA, TPB, SMEM_TOTAL>>>(ln_w, ln_b, out);
}

// round 5
// speedup vs baseline: 2.0238x; 2.0238x over previous
#include <cuda_runtime.h>
#include <cuda_fp16.h>
#include <cstdint>

#define BATCH 16
#define SEQ   256
#define DIM   512
#define G4    2048
#define LN_EPS 1e-5f

#define GROUPS 8                  // CTAs per batch
#define NCTA  (BATCH*GROUPS)     // 128
#define TPB   512
#define NWARP 16
#define KT    32                 // 16-wide k-tiles per row-block (512/16)
#define CKT   13                 // SMEM-cached k-tiles per layer per warp
#define WARP_CACHE_U4 (2*CKT*32)               // 832 uint4/warp
#define SMEM_W_BYTES (NWARP*WARP_CACHE_U4*16)  // 212992
#define OFF_H2  SMEM_W_BYTES                   // fp16 h buffer (1 KB)
#define OFF_RED (OFF_H2 + 1024)
#define OFF_C   (OFF_RED + NWARP*8)
#define SMEM_TOTAL (OFF_C + 16)

#define NFRAG ((size_t)BATCH*128*KT*32)        // uint4 fragment chunks (32 MB each)

// ---------------- static device scratch ----------------
__device__ uint4   d_w0f[NFRAG];              // whh0, A-fragment-major fp16
__device__ uint4   d_w1f[NFRAG];              // wih1+whh1, A-fragment-major fp16
__device__ float   d_pre0[(size_t)BATCH*SEQ*G4];
__device__ float   d_bias1[BATCH*G4];
__device__ float   d_gates[2*BATCH*G4];       // double-buffered by layer
__device__ float2  d_gstat[2*NCTA];
__device__ unsigned d_bar[BATCH*32];

// ---------------- helpers ----------------
__device__ __forceinline__ unsigned f2h2(float a, float b) {
    __half2 h = __floats2half2_rn(a, b);
    return *reinterpret_cast<unsigned*>(&h);
}
__device__ __forceinline__ unsigned long long pk2f(float x, float y) {
    unsigned long long r; asm("mov.b64 %0,{%1,%2};" : "=l"(r) : "f"(x), "f"(y)); return r;
}
__device__ __forceinline__ float2 upk2f(unsigned long long v) {
    float2 f; asm("mov.b64 {%0,%1},%2;" : "=f"(f.x), "=f"(f.y) : "l"(v)); return f;
}
__device__ __forceinline__ unsigned long long fma2(unsigned long long a,
                                                   unsigned long long b,
                                                   unsigned long long c) {
    unsigned long long d; asm("fma.rn.f32x2 %0,%1,%2,%3;" : "=l"(d) : "l"(a), "l"(b), "l"(c)); return d;
}
__device__ __forceinline__ float sigmoidf_(float x) {
    return __fdividef(1.f, 1.f + __expf(-x));
}

// ---------------- prep: build A-fragment-major fp16 weights ----------------
// chunk i -> lane=i&31, kt=(i>>5)&31, blk=(i>>10)&127, b=i>>17
// lane: gid=lane>>2 (row pair gid,gid+8), tig=lane&3 (logical cols 4tig..4tig+3)
// chunk = {row gid cols[4tig..+3] (8B), row gid+8 cols[4tig..+3] (8B)}
__global__ void prep_kernel(const float* __restrict__ whh0,
                            const float* __restrict__ wih1,
                            const float* __restrict__ whh1,
                            const float* __restrict__ bih1,
                            const float* __restrict__ bhh1)
{
    size_t idx0 = (size_t)blockIdx.x * blockDim.x + threadIdx.x;
    size_t stride = (size_t)gridDim.x * blockDim.x;
    for (size_t i = idx0; i < NFRAG; i += stride) {
        unsigned lane = (unsigned)i & 31u;
        unsigned kt   = ((unsigned)(i >> 5)) & 31u;
        unsigned blk  = ((unsigned)(i >> 10)) & 127u;
        unsigned b    = (unsigned)(i >> 17);
        unsigned gid  = lane >> 2, tig = lane & 3;
        size_t s0 = ((size_t)b * G4 + blk * 16 + gid) * DIM + kt * 16 + tig * 4;
        size_t s1 = s0 + 8 * DIM;
        {
            float4 A0 = *(const float4*)(whh0 + s0);
            float4 A1 = *(const float4*)(whh0 + s1);
            uint4 o;
            o.x = f2h2(A0.x, A0.y); o.y = f2h2(A0.z, A0.w);
            o.z = f2h2(A1.x, A1.y); o.w = f2h2(A1.z, A1.w);
            d_w0f[i] = o;
        }
        {
            float4 U0 = *(const float4*)(wih1 + s0);
            float4 V0 = *(const float4*)(whh1 + s0);
            float4 U1 = *(const float4*)(wih1 + s1);
            float4 V1 = *(const float4*)(whh1 + s1);
            uint4 o;
            o.x = f2h2(U0.x + V0.x, U0.y + V0.y); o.y = f2h2(U0.z + V0.z, U0.w + V0.w);
            o.z = f2h2(U1.x + V1.x, U1.y + V1.y); o.w = f2h2(U1.z + V1.z, U1.w + V1.w);
            d_w1f[i] = o;
        }
    }
    if (idx0 < BATCH * G4) d_bias1[idx0] = bih1[idx0] + bhh1[idx0];
    if (idx0 < BATCH * 32) d_bar[idx0] = 0u;
}

// ---- SGEMM (f32x2): d_pre0[b][t][j] = wih0[b]@x[b,t] + bih0 + bhh0 ----
__global__ void __launch_bounds__(256) gemm_pre0(const float* __restrict__ x,
                                                 const float* __restrict__ wih0,
                                                 const float* __restrict__ bih0,
                                                 const float* __restrict__ bhh0)
{
    __shared__ float As[16][132];
    __shared__ float Bs[16][132];
    const int b  = blockIdx.y;
    const int mt = blockIdx.x & 15;
    const int nt = blockIdx.x >> 4;
    const float* A = wih0 + ((size_t)b * G4  + (size_t)mt * 128) * DIM;
    const float* B = x    + ((size_t)b * SEQ + (size_t)nt * 128) * DIM;
    const int tid = threadIdx.x;
    const int tr = tid & 15;
    const int tc = tid >> 4;

    unsigned long long acc2[8][4];
#pragma unroll
    for (int i = 0; i < 8; i++)
#pragma unroll
        for (int j = 0; j < 4; j++) acc2[i][j] = 0ull;

    for (int k0 = 0; k0 < DIM; k0 += 16) {
        __syncthreads();
#pragma unroll
        for (int p = 0; p < 2; p++) {
            int fid = tid + p * 256;
            int row = fid >> 2;
            int kq  = fid & 3;
            float4 va = *(const float4*)(A + (size_t)row * DIM + k0 + kq * 4);
            As[kq*4+0][row] = va.x; As[kq*4+1][row] = va.y;
            As[kq*4+2][row] = va.z; As[kq*4+3][row] = va.w;
            float4 vb = *(const float4*)(B + (size_t)row * DIM + k0 + kq * 4);
            Bs[kq*4+0][row] = vb.x; Bs[kq*4+1][row] = vb.y;
            Bs[kq*4+2][row] = vb.z; Bs[kq*4+3][row] = vb.w;
        }
        __syncthreads();
#pragma unroll
        for (int kk = 0; kk < 16; kk++) {
            float4 a0 = *(const float4*)&As[kk][tr*4];
            float4 a1 = *(const float4*)&As[kk][64 + tr*4];
            float4 b0 = *(const float4*)&Bs[kk][tc*4];
            float4 b1 = *(const float4*)&Bs[kk][64 + tc*4];
            float af[8] = {a0.x,a0.y,a0.z,a0.w,a1.x,a1.y,a1.z,a1.w};
            unsigned long long bp[4];
            bp[0] = pk2f(b0.x, b0.y); bp[1] = pk2f(b0.z, b0.w);
            bp[2] = pk2f(b1.x, b1.y); bp[3] = pk2f(b1.z, b1.w);
#pragma unroll
            for (int i = 0; i < 8; i++) {
                unsigned long long ap = pk2f(af[i], af[i]);
#pragma unroll
                for (int j = 0; j < 4; j++)
                    acc2[i][j] = fma2(ap, bp[j], acc2[i][j]);
            }
        }
    }

    float acc[8][8];
#pragma unroll
    for (int i = 0; i < 8; i++)
#pragma unroll
        for (int j = 0; j < 4; j++) {
            float2 f = upk2f(acc2[i][j]);
            acc[i][2*j] = f.x; acc[i][2*j+1] = f.y;
        }

    float biasv[8];
#pragma unroll
    for (int i = 0; i < 8; i++) {
        int j = mt * 128 + ((i < 4) ? (tr*4 + i) : (64 + tr*4 + (i - 4)));
        biasv[i] = bih0[b * G4 + j] + bhh0[b * G4 + j];
    }
#pragma unroll
    for (int jj = 0; jj < 8; jj++) {
        int t = nt * 128 + ((jj < 4) ? (tc*4 + jj) : (64 + tc*4 + (jj - 4)));
        float* dst = &d_pre0[((size_t)b * SEQ + t) * G4 + mt * 128];
        float4 v0, v1;
        v0.x = acc[0][jj] + biasv[0]; v0.y = acc[1][jj] + biasv[1];
        v0.z = acc[2][jj] + biasv[2]; v0.w = acc[3][jj] + biasv[3];
        v1.x = acc[4][jj] + biasv[4]; v1.y = acc[5][jj] + biasv[5];
        v1.z = acc[6][jj] + biasv[6]; v1.w = acc[7][jj] + biasv[7];
        *(float4*)(dst + tr * 4)      = v0;
        *(float4*)(dst + 64 + tr * 4) = v1;
    }
}

// ---------------- persistent LSTM kernel (HMMA matvec, L2 barrier) ----------------
__device__ __forceinline__ void group_barrier(volatile unsigned* bar, unsigned* epoch, int tid) {
    __syncthreads();
    *epoch += GROUPS;
    unsigned target = *epoch;
    if (tid == 0) {
        __threadfence();
        atomicAdd((unsigned*)bar, 1u);
        while (*bar < target) { }
        __threadfence();
    }
    __syncthreads();
}

#define MMA16816(d, v, hb)                                                        \
    asm volatile("mma.sync.aligned.m16n8k16.row.col.f32.f16.f16.f32 "             \
                 "{%0,%1,%2,%3},{%4,%5,%6,%7},{%8,%9},{%0,%1,%2,%3};"             \
                 : "+f"(d[0]), "+f"(d[1]), "+f"(d[2]), "+f"(d[3])                 \
                 : "r"(v.x), "r"(v.z), "r"(v.y), "r"(v.w), "r"(hb.x), "r"(hb.y))

__global__ void __launch_bounds__(TPB, 1)
lstm_kernel(const float* __restrict__ lnw, const float* __restrict__ lnb,
            float* __restrict__ out)
{
    extern __shared__ __align__(16) unsigned char smem[];
    uint4*  s_w   = (uint4*)smem;
    __half* s_h2  = (__half*)(smem + OFF_H2);
    float2* s_red = (float2*)(smem + OFF_RED);
    float*  s_c   = (float*)(smem + OFF_C);

    const int cta = blockIdx.x;
    const int b   = cta >> 3;
    const int k   = cta & 7;
    const int tid = threadIdx.x;
    const int wid = tid >> 5;
    const int lane = tid & 31;
    const int gid = lane >> 2;
    const int tig = lane & 3;

    volatile unsigned* bar = &d_bar[b * 32];
    unsigned epoch = 0;
    const int blk  = k * 16 + wid;        // global 16-row block id within batch
    const int row0 = blk * 16;

    // ---- fill SMEM fragment cache: per warp, tiles 0..CKT-1 of each layer ----
    for (int i = tid; i < NWARP * WARP_CACHE_U4; i += TPB) {
        int w  = i / WARP_CACHE_U4;
        int r  = i % WARP_CACHE_U4;
        int l  = r / (CKT * 32);
        int rr = r % (CKT * 32);           // kt*32 + lane
        const uint4* src = (l ? d_w1f : d_w0f)
                         + ((size_t)b * 128 + k * 16 + w) * (KT * 32) + rr;
        s_w[i] = *src;
    }

    const float gw0 = __ldg(lnw + tid),       gb0 = __ldg(lnb + tid);
    const float gw1 = __ldg(lnw + DIM + tid), gb1 = __ldg(lnb + DIM + tid);

    float creg = 0.f;
    ((unsigned short*)s_h2)[tid] = 0;      // h = 0 (fp16)
    __syncthreads();

    for (int t = 0; t < SEQ; t++) {
#pragma unroll
        for (int l = 0; l < 2; l++) {
            const float* add = (l == 0) ? (d_pre0 + ((size_t)b * SEQ + t) * G4)
                                        : (d_bias1 + (size_t)b * G4);
            float* gates = d_gates + (size_t)l * BATCH * G4 + (size_t)b * G4;
            const uint4* Wg = (l ? d_w1f : d_w0f) + ((size_t)b * 128 + blk) * (KT * 32);
            const uint4* Ws = s_w + wid * WARP_CACHE_U4 + l * (CKT * 32);
            const char* hbp = (const char*)s_h2 + tig * 8;

            float da[4] = {0.f, 0.f, 0.f, 0.f};
            float db[4] = {0.f, 0.f, 0.f, 0.f};
#pragma unroll
            for (int kt = 0; kt < KT; kt++) {
                uint4 v = (kt < CKT) ? Ws[kt * 32 + lane]
                                     : __ldcg(&Wg[kt * 32 + lane]);
                uint2 hb = *(const uint2*)(hbp + kt * 32);
                if (kt & 1) { MMA16816(db, v, hb); }
                else        { MMA16816(da, v, hb); }
            }
            // every lane's D col is the gate (h replicated over columns)
            float g0 = da[0] + db[0] + __ldg(add + row0 + gid);
            float g1 = da[2] + db[2] + __ldg(add + row0 + 8 + gid);
            if (tig == 0) {
                gates[row0 + gid]     = g0;
                gates[row0 + 8 + gid] = g1;
            }
            float s1 = g0 + g1;
            float s2 = fmaf(g0, g0, g1 * g1);
#pragma unroll
            for (int o = 16; o >= 4; o >>= 1) {      // sums lanes 0,4,...,28
                s1 += __shfl_down_sync(0xffffffffu, s1, o);
                s2 += __shfl_down_sync(0xffffffffu, s2, o);
            }
            if (lane == 0) s_red[wid] = make_float2(s1, s2);
            __syncthreads();
            if (tid == 0) {
                float a = 0.f, c = 0.f;
#pragma unroll
                for (int i = 0; i < NWARP; i++) { a += s_red[i].x; c += s_red[i].y; }
                d_gstat[l * NCTA + cta] = make_float2(a, c);
            }
            group_barrier(bar, &epoch, tid);

            // ---- pointwise (redundant per CTA) ----
            {
                const int d = tid;
                const float gw = (l == 0) ? gw0 : gw1;
                const float gb = (l == 0) ? gb0 : gb1;
                const float4* st4 = (const float4*)(&d_gstat[l * NCTA + b * 8]);
                float m_[4], r_[4];
#pragma unroll
                for (int q = 0; q < 4; q++) {
                    float4 sv = __ldcg(st4 + q);
                    float s  = sv.x + sv.z;
                    float ss = sv.y + sv.w;
                    float m  = s * (1.f / 512.f);
                    float v  = fmaf(-m, m, ss * (1.f / 512.f));
                    m_[q] = m;
                    r_[q] = rsqrtf(v + LN_EPS);
                }
                float xi = __ldcg(gates + d);
                float xf = __ldcg(gates + 512 + d);
                float xg = __ldcg(gates + 1024 + d);
                float xo = __ldcg(gates + 1536 + d);
                float iv = sigmoidf_(fmaf((xi - m_[0]) * r_[0], gw, gb));
                float fv = sigmoidf_(fmaf((xf - m_[1]) * r_[1], gw, gb));
                float gv = tanhf(    fmaf((xg - m_[2]) * r_[2], gw, gb));
                float ov = sigmoidf_(fmaf((xo - m_[3]) * r_[3], gw, gb));
                float cn = fmaf(fv, creg, iv * gv);
                creg = cn;

                float a = cn, c2 = cn * cn;
#pragma unroll
                for (int o = 16; o > 0; o >>= 1) {
                    a  += __shfl_down_sync(0xffffffffu, a, o);
                    c2 += __shfl_down_sync(0xffffffffu, c2, o);
                }
                if (lane == 0) s_red[wid] = make_float2(a, c2);
                __syncthreads();
                if (tid == 0) {
                    float sa = 0.f, sb = 0.f;
#pragma unroll
                    for (int i = 0; i < NWARP; i++) { sa += s_red[i].x; sb += s_red[i].y; }
                    float m = sa * (1.f / 512.f);
                    float v = fmaf(-m, m, sb * (1.f / 512.f));
                    s_c[0] = m;
                    s_c[1] = rsqrtf(v + LN_EPS);
                }
                __syncthreads();
                float hv = ov * tanhf(fmaf((cn - s_c[0]) * s_c[1], gw, gb));
                s_h2[d] = __float2half_rn(hv);
                if (l == 1 && k == 0)
                    out[((size_t)b * SEQ + t) * DIM + d] = hv;
                __syncthreads();   // s_h2 ready before next matvec
            }
        }
    }
}

extern "C" void kernel_launch(void* const* d_in, const int* in_sizes, int n_in,
                              void* d_out, int out_size) {
    const float* x    = (const float*)d_in[0];
    const float* wih0 = (const float*)d_in[1];
    const float* whh0 = (const float*)d_in[2];
    const float* bih0 = (const float*)d_in[3];
    const float* bhh0 = (const float*)d_in[4];
    const float* wih1 = (const float*)d_in[5];
    const float* whh1 = (const float*)d_in[6];
    const float* bih1 = (const float*)d_in[7];
    const float* bhh1 = (const float*)d_in[8];
    const float* ln_w = (const float*)d_in[9];
    const float* ln_b = (const float*)d_in[10];
    float* out = (float*)d_out;

    cudaFuncSetAttribute(lstm_kernel, cudaFuncAttributeMaxDynamicSharedMemorySize,
                         SMEM_TOTAL);

    prep_kernel<<<1024, 256>>>(whh0, wih1, whh1, bih1, bhh1);
    gemm_pre0<<<dim3(32, 16), 256>>>(x, wih0, bih0, bhh0);
    lstm_kernel<<<NCTA, TPB, SMEM_TOTAL>>>(ln_w, ln_b, out);
}

// round 6
// speedup vs baseline: 2.1876x; 1.0809x over previous
#include <cuda_runtime.h>
#include <cuda_fp16.h>
#include <cstdint>

#define BATCH 16
#define SEQ   256
#define DIM   512
#define G4    2048
#define LN_EPS 1e-5f

#define GROUPS 8                  // CTAs per batch
#define NCTA  (BATCH*GROUPS)     // 128
#define TPB   512
#define NWARP 16
#define KT    32                 // 16-wide k-tiles per row-block (512/16)
#define CKT   13                 // SMEM-cached k-tiles per layer per warp
#define PF    6                  // register-prefetched streamed tiles
#define WARP_CACHE_U4 (2*CKT*32)               // 832 uint4/warp
#define SMEM_W_BYTES (NWARP*WARP_CACHE_U4*16)  // 212992
#define OFF_H2  SMEM_W_BYTES                   // fp16 h buffer (1 KB)
#define OFF_RED (OFF_H2 + 1024)
#define OFF_C   (OFF_RED + NWARP*8)
#define SMEM_TOTAL (OFF_C + 16)

#define NFRAG ((size_t)BATCH*128*KT*32)        // uint4 fragment chunks (32 MB each)

// ---------------- static device scratch ----------------
__device__ uint4   d_w0f[NFRAG];              // whh0, A-fragment-major fp16
__device__ uint4   d_w1f[NFRAG];              // wih1+whh1, A-fragment-major fp16
__device__ float   d_pre0[(size_t)BATCH*SEQ*G4];
__device__ float   d_bias1[BATCH*G4];
__device__ float   d_gates[2*BATCH*G4];       // double-buffered by layer
__device__ float2  d_gstat[2*NCTA];
__device__ unsigned d_bar[BATCH*32];

// ---------------- helpers ----------------
__device__ __forceinline__ unsigned f2h2(float a, float b) {
    __half2 h = __floats2half2_rn(a, b);
    return *reinterpret_cast<unsigned*>(&h);
}
__device__ __forceinline__ unsigned long long pk2f(float x, float y) {
    unsigned long long r; asm("mov.b64 %0,{%1,%2};" : "=l"(r) : "f"(x), "f"(y)); return r;
}
__device__ __forceinline__ float2 upk2f(unsigned long long v) {
    float2 f; asm("mov.b64 {%0,%1},%2;" : "=f"(f.x), "=f"(f.y) : "l"(v)); return f;
}
__device__ __forceinline__ unsigned long long fma2(unsigned long long a,
                                                   unsigned long long b,
                                                   unsigned long long c) {
    unsigned long long d; asm("fma.rn.f32x2 %0,%1,%2,%3;" : "=l"(d) : "l"(a), "l"(b), "l"(c)); return d;
}
__device__ __forceinline__ float sigmoidf_(float x) {
    return __fdividef(1.f, 1.f + __expf(-x));
}
__device__ __forceinline__ float tanhf_(float x) {
    x = fminf(fmaxf(x, -12.f), 12.f);
    float t = __expf(2.f * x);
    return __fdividef(t - 1.f, t + 1.f);
}

// ---------------- prep: build A-fragment-major fp16 weights ----------------
__global__ void prep_kernel(const float* __restrict__ whh0,
                            const float* __restrict__ wih1,
                            const float* __restrict__ whh1,
                            const float* __restrict__ bih1,
                            const float* __restrict__ bhh1)
{
    size_t idx0 = (size_t)blockIdx.x * blockDim.x + threadIdx.x;
    size_t stride = (size_t)gridDim.x * blockDim.x;
    for (size_t i = idx0; i < NFRAG; i += stride) {
        unsigned lane = (unsigned)i & 31u;
        unsigned kt   = ((unsigned)(i >> 5)) & 31u;
        unsigned blk  = ((unsigned)(i >> 10)) & 127u;
        unsigned b    = (unsigned)(i >> 17);
        unsigned gid  = lane >> 2, tig = lane & 3;
        size_t s0 = ((size_t)b * G4 + blk * 16 + gid) * DIM + kt * 16 + tig * 4;
        size_t s1 = s0 + 8 * DIM;
        {
            float4 A0 = *(const float4*)(whh0 + s0);
            float4 A1 = *(const float4*)(whh0 + s1);
            uint4 o;
            o.x = f2h2(A0.x, A0.y); o.y = f2h2(A0.z, A0.w);
            o.z = f2h2(A1.x, A1.y); o.w = f2h2(A1.z, A1.w);
            d_w0f[i] = o;
        }
        {
            float4 U0 = *(const float4*)(wih1 + s0);
            float4 V0 = *(const float4*)(whh1 + s0);
            float4 U1 = *(const float4*)(wih1 + s1);
            float4 V1 = *(const float4*)(whh1 + s1);
            uint4 o;
            o.x = f2h2(U0.x + V0.x, U0.y + V0.y); o.y = f2h2(U0.z + V0.z, U0.w + V0.w);
            o.z = f2h2(U1.x + V1.x, U1.y + V1.y); o.w = f2h2(U1.z + V1.z, U1.w + V1.w);
            d_w1f[i] = o;
        }
    }
    if (idx0 < BATCH * G4) d_bias1[idx0] = bih1[idx0] + bhh1[idx0];
    if (idx0 < BATCH * 32) d_bar[idx0] = 0u;
}

// ---- SGEMM (f32x2): d_pre0[b][t][j] = wih0[b]@x[b,t] + bih0 + bhh0 ----
__global__ void __launch_bounds__(256) gemm_pre0(const float* __restrict__ x,
                                                 const float* __restrict__ wih0,
                                                 const float* __restrict__ bih0,
                                                 const float* __restrict__ bhh0)
{
    __shared__ float As[16][132];
    __shared__ float Bs[16][132];
    const int b  = blockIdx.y;
    const int mt = blockIdx.x & 15;
    const int nt = blockIdx.x >> 4;
    const float* A = wih0 + ((size_t)b * G4  + (size_t)mt * 128) * DIM;
    const float* B = x    + ((size_t)b * SEQ + (size_t)nt * 128) * DIM;
    const int tid = threadIdx.x;
    const int tr = tid & 15;
    const int tc = tid >> 4;

    unsigned long long acc2[8][4];
#pragma unroll
    for (int i = 0; i < 8; i++)
#pragma unroll
        for (int j = 0; j < 4; j++) acc2[i][j] = 0ull;

    for (int k0 = 0; k0 < DIM; k0 += 16) {
        __syncthreads();
#pragma unroll
        for (int p = 0; p < 2; p++) {
            int fid = tid + p * 256;
            int row = fid >> 2;
            int kq  = fid & 3;
            float4 va = *(const float4*)(A + (size_t)row * DIM + k0 + kq * 4);
            As[kq*4+0][row] = va.x; As[kq*4+1][row] = va.y;
            As[kq*4+2][row] = va.z; As[kq*4+3][row] = va.w;
            float4 vb = *(const float4*)(B + (size_t)row * DIM + k0 + kq * 4);
            Bs[kq*4+0][row] = vb.x; Bs[kq*4+1][row] = vb.y;
            Bs[kq*4+2][row] = vb.z; Bs[kq*4+3][row] = vb.w;
        }
        __syncthreads();
#pragma unroll
        for (int kk = 0; kk < 16; kk++) {
            float4 a0 = *(const float4*)&As[kk][tr*4];
            float4 a1 = *(const float4*)&As[kk][64 + tr*4];
            float4 b0 = *(const float4*)&Bs[kk][tc*4];
            float4 b1 = *(const float4*)&Bs[kk][64 + tc*4];
            float af[8] = {a0.x,a0.y,a0.z,a0.w,a1.x,a1.y,a1.z,a1.w};
            unsigned long long bp[4];
            bp[0] = pk2f(b0.x, b0.y); bp[1] = pk2f(b0.z, b0.w);
            bp[2] = pk2f(b1.x, b1.y); bp[3] = pk2f(b1.z, b1.w);
#pragma unroll
            for (int i = 0; i < 8; i++) {
                unsigned long long ap = pk2f(af[i], af[i]);
#pragma unroll
                for (int j = 0; j < 4; j++)
                    acc2[i][j] = fma2(ap, bp[j], acc2[i][j]);
            }
        }
    }

    float acc[8][8];
#pragma unroll
    for (int i = 0; i < 8; i++)
#pragma unroll
        for (int j = 0; j < 4; j++) {
            float2 f = upk2f(acc2[i][j]);
            acc[i][2*j] = f.x; acc[i][2*j+1] = f.y;
        }

    float biasv[8];
#pragma unroll
    for (int i = 0; i < 8; i++) {
        int j = mt * 128 + ((i < 4) ? (tr*4 + i) : (64 + tr*4 + (i - 4)));
        biasv[i] = bih0[b * G4 + j] + bhh0[b * G4 + j];
    }
#pragma unroll
    for (int jj = 0; jj < 8; jj++) {
        int t = nt * 128 + ((jj < 4) ? (tc*4 + jj) : (64 + tc*4 + (jj - 4)));
        float* dst = &d_pre0[((size_t)b * SEQ + t) * G4 + mt * 128];
        float4 v0, v1;
        v0.x = acc[0][jj] + biasv[0]; v0.y = acc[1][jj] + biasv[1];
        v0.z = acc[2][jj] + biasv[2]; v0.w = acc[3][jj] + biasv[3];
        v1.x = acc[4][jj] + biasv[4]; v1.y = acc[5][jj] + biasv[5];
        v1.z = acc[6][jj] + biasv[6]; v1.w = acc[7][jj] + biasv[7];
        *(float4*)(dst + tr * 4)      = v0;
        *(float4*)(dst + 64 + tr * 4) = v1;
    }
}

// ---------------- persistent LSTM kernel (HMMA matvec, acq/rel barrier) ----------------
__device__ __forceinline__ void group_barrier(unsigned* bar, unsigned* epoch, int tid) {
    __syncthreads();
    *epoch += GROUPS;
    unsigned target = *epoch;
    if (tid == 0) {
        asm volatile("red.release.gpu.global.add.u32 [%0],%1;"
                     :: "l"(bar), "r"(1u) : "memory");
        unsigned v;
        do {
            asm volatile("ld.acquire.gpu.global.u32 %0,[%1];"
                         : "=r"(v) : "l"(bar) : "memory");
        } while (v < target);
    }
    __syncthreads();
}

#define MMA16816(d, v, hb)                                                        \
    asm volatile("mma.sync.aligned.m16n8k16.row.col.f32.f16.f16.f32 "             \
                 "{%0,%1,%2,%3},{%4,%5,%6,%7},{%8,%9},{%0,%1,%2,%3};"             \
                 : "+f"(d[0]), "+f"(d[1]), "+f"(d[2]), "+f"(d[3])                 \
                 : "r"(v.x), "r"(v.z), "r"(v.y), "r"(v.w), "r"(hb.x), "r"(hb.y))

__global__ void __launch_bounds__(TPB, 1)
lstm_kernel(const float* __restrict__ lnw, const float* __restrict__ lnb,
            float* __restrict__ out)
{
    extern __shared__ __align__(16) unsigned char smem[];
    uint4*  s_w   = (uint4*)smem;
    __half* s_h2  = (__half*)(smem + OFF_H2);
    float2* s_red = (float2*)(smem + OFF_RED);
    float*  s_c   = (float*)(smem + OFF_C);

    const int cta = blockIdx.x;
    const int b   = cta >> 3;
    const int k   = cta & 7;
    const int tid = threadIdx.x;
    const int wid = tid >> 5;
    const int lane = tid & 31;
    const int gid = lane >> 2;
    const int tig = lane & 3;

    unsigned* bar = &d_bar[b * 32];
    unsigned epoch = 0;
    const int blk  = k * 16 + wid;        // global 16-row block id within batch
    const int row0 = blk * 16;

    // per-layer streamed-weight base pointers for this warp
    const uint4* Wg0 = d_w0f + ((size_t)b * 128 + blk) * (KT * 32);
    const uint4* Wg1 = d_w1f + ((size_t)b * 128 + blk) * (KT * 32);

    // ---- fill SMEM fragment cache: per warp, tiles 0..CKT-1 of each layer ----
    for (int i = tid; i < NWARP * WARP_CACHE_U4; i += TPB) {
        int w  = i / WARP_CACHE_U4;
        int r  = i % WARP_CACHE_U4;
        int l  = r / (CKT * 32);
        int rr = r % (CKT * 32);           // kt*32 + lane
        const uint4* src = (l ? d_w1f : d_w0f)
                         + ((size_t)b * 128 + k * 16 + w) * (KT * 32) + rr;
        s_w[i] = *src;
    }

    const float gw0 = __ldg(lnw + tid),       gb0 = __ldg(lnb + tid);
    const float gw1 = __ldg(lnw + DIM + tid), gb1 = __ldg(lnb + DIM + tid);

    float creg = 0.f;
    ((unsigned short*)s_h2)[tid] = 0;      // h = 0 (fp16)

    // initial prefetch for (t=0, l=0)
    uint4 pf[PF];
#pragma unroll
    for (int j = 0; j < PF; j++) pf[j] = __ldcg(&Wg0[(CKT + j) * 32 + lane]);

    __syncthreads();

    for (int t = 0; t < SEQ; t++) {
#pragma unroll
        for (int l = 0; l < 2; l++) {
            const float* add = (l == 0) ? (d_pre0 + ((size_t)b * SEQ + t) * G4)
                                        : (d_bias1 + (size_t)b * G4);
            float* gates = d_gates + (size_t)l * BATCH * G4 + (size_t)b * G4;
            const uint4* Wg = l ? Wg1 : Wg0;
            const uint4* Ws = s_w + wid * WARP_CACHE_U4 + l * (CKT * 32);
            const char* hbp = (const char*)s_h2 + tig * 8;

            float da[4] = {0.f, 0.f, 0.f, 0.f};
            float db[4] = {0.f, 0.f, 0.f, 0.f};
#pragma unroll
            for (int kt = 0; kt < KT; kt++) {
                uint4 v = (kt < CKT) ? Ws[kt * 32 + lane]
                        : (kt < CKT + PF) ? pf[kt - CKT]
                                          : __ldcg(&Wg[kt * 32 + lane]);
                uint2 hb = *(const uint2*)(hbp + kt * 32);
                if (kt & 1) { MMA16816(db, v, hb); }
                else        { MMA16816(da, v, hb); }
            }
            // every lane's D col is the gate (h replicated over columns)
            float g0 = da[0] + db[0] + __ldg(add + row0 + gid);
            float g1 = da[2] + db[2] + __ldg(add + row0 + 8 + gid);
            if (tig == 0) {
                gates[row0 + gid]     = g0;
                gates[row0 + 8 + gid] = g1;
            }
            float s1 = g0 + g1;
            float s2 = fmaf(g0, g0, g1 * g1);
#pragma unroll
            for (int o = 16; o >= 4; o >>= 1) {      // sums lanes 0,4,...,28
                s1 += __shfl_down_sync(0xffffffffu, s1, o);
                s2 += __shfl_down_sync(0xffffffffu, s2, o);
            }
            if (lane == 0) s_red[wid] = make_float2(s1, s2);
            __syncthreads();
            if (tid == 0) {
                float a = 0.f, c = 0.f;
#pragma unroll
                for (int i = 0; i < NWARP; i++) { a += s_red[i].x; c += s_red[i].y; }
                d_gstat[l * NCTA + cta] = make_float2(a, c);
            }
            group_barrier(bar, &epoch, tid);

            // ---- prefetch streamed tiles for the NEXT matvec (weights are static) ----
            {
                const uint4* Wn = l ? Wg0 : Wg1;   // next layer (wraps to l=0 next t)
#pragma unroll
                for (int j = 0; j < PF; j++) pf[j] = __ldcg(&Wn[(CKT + j) * 32 + lane]);
            }

            // ---- pointwise (redundant per CTA) ----
            {
                const int d = tid;
                const float gw = (l == 0) ? gw0 : gw1;
                const float gb = (l == 0) ? gb0 : gb1;
                const float4* st4 = (const float4*)(&d_gstat[l * NCTA + b * 8]);
                float m_[4], r_[4];
#pragma unroll
                for (int q = 0; q < 4; q++) {
                    float4 sv = __ldcg(st4 + q);
                    float s  = sv.x + sv.z;
                    float ss = sv.y + sv.w;
                    float m  = s * (1.f / 512.f);
                    float v  = fmaf(-m, m, ss * (1.f / 512.f));
                    m_[q] = m;
                    r_[q] = rsqrtf(v + LN_EPS);
                }
                float xi = __ldcg(gates + d);
                float xf = __ldcg(gates + 512 + d);
                float xg = __ldcg(gates + 1024 + d);
                float xo = __ldcg(gates + 1536 + d);
                float iv = sigmoidf_(fmaf((xi - m_[0]) * r_[0], gw, gb));
                float fv = sigmoidf_(fmaf((xf - m_[1]) * r_[1], gw, gb));
                float gv = tanhf_(   fmaf((xg - m_[2]) * r_[2], gw, gb));
                float ov = sigmoidf_(fmaf((xo - m_[3]) * r_[3], gw, gb));
                float cn = fmaf(fv, creg, iv * gv);
                creg = cn;

                float a = cn, c2 = cn * cn;
#pragma unroll
                for (int o = 16; o > 0; o >>= 1) {
                    a  += __shfl_down_sync(0xffffffffu, a, o);
                    c2 += __shfl_down_sync(0xffffffffu, c2, o);
                }
                if (lane == 0) s_red[wid] = make_float2(a, c2);
                __syncthreads();
                if (tid == 0) {
                    float sa = 0.f, sb = 0.f;
#pragma unroll
                    for (int i = 0; i < NWARP; i++) { sa += s_red[i].x; sb += s_red[i].y; }
                    float m = sa * (1.f / 512.f);
                    float v = fmaf(-m, m, sb * (1.f / 512.f));
                    s_c[0] = m;
                    s_c[1] = rsqrtf(v + LN_EPS);
                }
                __syncthreads();
                float hv = ov * tanhf_(fmaf((cn - s_c[0]) * s_c[1], gw, gb));
                s_h2[d] = __float2half_rn(hv);
                if (l == 1 && k == 0)
                    out[((size_t)b * SEQ + t) * DIM + d] = hv;
                __syncthreads();   // s_h2 ready before next matvec
            }
        }
    }
}

extern "C" void kernel_launch(void* const* d_in, const int* in_sizes, int n_in,
                              void* d_out, int out_size) {
    const float* x    = (const float*)d_in[0];
    const float* wih0 = (const float*)d_in[1];
    const float* whh0 = (const float*)d_in[2];
    const float* bih0 = (const float*)d_in[3];
    const float* bhh0 = (const float*)d_in[4];
    const float* wih1 = (const float*)d_in[5];
    const float* whh1 = (const float*)d_in[6];
    const float* bih1 = (const float*)d_in[7];
    const float* bhh1 = (const float*)d_in[8];
    const float* ln_w = (const float*)d_in[9];
    const float* ln_b = (const float*)d_in[10];
    float* out = (float*)d_out;

    cudaFuncSetAttribute(lstm_kernel, cudaFuncAttributeMaxDynamicSharedMemorySize,
                         SMEM_TOTAL);

    prep_kernel<<<1024, 256>>>(whh0, wih1, whh1, bih1, bhh1);
    gemm_pre0<<<dim3(32, 16), 256>>>(x, wih0, bih0, bhh0);
    lstm_kernel<<<NCTA, TPB, SMEM_TOTAL>>>(ln_w, ln_b, out);
}